// round 6
// baseline (speedup 1.0000x reference)
#include <cuda_runtime.h>
#include <cstdint>

// Problem constants (fixed by the reference)
#define BB 32
#define QQ 900
#define CC 92
#define BIGV 100000000.0f
#define TI 20            // i-rows per block
#define JBLK 450         // j-span per block (Q = 2 * 450)
#define JT 225           // active threads per block (2 j's each)

// Scratch: softmax stores (1 - prob) for FFMA folding in the cost kernel.
__device__ float g_nprobs[BB * QQ * CC];

__device__ __forceinline__ float fast_rcp(float x) {
    float r;
    asm("rcp.approx.ftz.f32 %0, %1;" : "=f"(r) : "f"(x));
    return r;
}

// ---------------------------------------------------------------------------
// Kernel 1: row softmax, stores (1 - p). One warp per (b,i) row of 92 logits.
// ---------------------------------------------------------------------------
__global__ void softmax_rows_kernel(const float* __restrict__ logits) {
    int gwarp = (blockIdx.x * blockDim.x + threadIdx.x) >> 5;
    int lane  = threadIdx.x & 31;
    if (gwarp >= BB * QQ) return;

    const float* in = logits + (size_t)gwarp * CC;
    float v0 = in[lane];
    float v1 = in[lane + 32];
    bool has2 = lane < (CC - 64);          // lane < 28
    float v2 = has2 ? in[lane + 64] : -1e30f;

    float m = fmaxf(fmaxf(v0, v1), v2);
    #pragma unroll
    for (int o = 16; o > 0; o >>= 1)
        m = fmaxf(m, __shfl_xor_sync(0xFFFFFFFFu, m, o));

    float e0 = __expf(v0 - m);
    float e1 = __expf(v1 - m);
    float e2 = has2 ? __expf(v2 - m) : 0.0f;
    float s = e0 + e1 + e2;
    #pragma unroll
    for (int o = 16; o > 0; o >>= 1)
        s += __shfl_xor_sync(0xFFFFFFFFu, s, o);

    float inv = __fdividef(1.0f, s);
    float* outp = g_nprobs + (size_t)gwarp * CC;
    outp[lane]      = fmaf(e0, -inv, 1.0f);
    outp[lane + 32] = fmaf(e1, -inv, 1.0f);
    if (has2) outp[lane + 64] = fmaf(e2, -inv, 1.0f);
}

// ---------------------------------------------------------------------------
// Kernel 2: cost matrix. Block = (i-tile, j-half, batch).
// Each thread owns 2 consecutive j (low regs -> high occupancy) and emits
// TI float2 stores.
//   cost = 0.25*L1 + (1 - prob) - inter/uni - uni/enc
// ---------------------------------------------------------------------------
__global__ __launch_bounds__(256)
void cost_kernel(const float* __restrict__ pred_boxes,
                 const float* __restrict__ boxes,
                 const float* __restrict__ area,
                 const int*   __restrict__ labels,
                 float* __restrict__ out) {
    const int b   = blockIdx.z;
    const int i0  = blockIdx.x * TI;
    const int jb  = blockIdx.y * JBLK;
    const int tid = threadIdx.x;

    __shared__ float  s_np[TI][CC];     // (1 - prob) rows for the i-tile
    __shared__ float4 s_c[TI];          // pred box cxcywh
    __shared__ float4 s_x[TI];          // pred box xyxy
    __shared__ float  s_a1[TI];         // pred box area (w*h)

    for (int k = tid; k < TI * CC; k += 256) {
        int ii = k / CC;
        int c  = k - ii * CC;
        s_np[ii][c] = g_nprobs[((size_t)(b * QQ + i0 + ii)) * CC + c];
    }
    if (tid < TI) {
        float4 pb = reinterpret_cast<const float4*>(pred_boxes)[b * QQ + i0 + tid];
        s_c[tid] = pb;
        s_x[tid] = make_float4(pb.x - 0.5f * pb.z, pb.y - 0.5f * pb.w,
                               pb.x + 0.5f * pb.z, pb.y + 0.5f * pb.w);
        s_a1[tid] = pb.z * pb.w;
    }
    __syncthreads();

    if (tid >= JT) return;              // 225 active threads cover 450 j's
    const int j0 = jb + tid * 2;

    float4 gb[2];
    float gx0[2], gy0[2], gx1[2], gy1[2], a2[2];
    bool  valid[2];
    const float* npcol[2];              // &s_np[0][lab[t]]
    #pragma unroll
    for (int t = 0; t < 2; t++) {
        gb[t] = reinterpret_cast<const float4*>(boxes)[b * QQ + j0 + t];
        int lab = labels[b * QQ + j0 + t];
        npcol[t] = &s_np[0][lab];
        valid[t] = area[b * QQ + j0 + t] > 0.0f;
        gx0[t] = gb[t].x - 0.5f * gb[t].z; gy0[t] = gb[t].y - 0.5f * gb[t].w;
        gx1[t] = gb[t].x + 0.5f * gb[t].z; gy1[t] = gb[t].y + 0.5f * gb[t].w;
        a2[t]  = gb[t].z * gb[t].w;
    }

    float* obase = out + ((size_t)(b * QQ + i0)) * QQ + j0;

    #pragma unroll 5
    for (int ii = 0; ii < TI; ii++) {
        float4 pc = s_c[ii];
        float4 px = s_x[ii];
        float  a1 = s_a1[ii];
        float2 res;
        float* r = &res.x;
        #pragma unroll
        for (int t = 0; t < 2; t++) {
            // mean-L1 (x0.25 folded into final FFMA)
            float d0 = pc.x - gb[t].x, d1 = pc.y - gb[t].y;
            float d2 = pc.z - gb[t].z, d3 = pc.w - gb[t].w;
            float L1 = (fabsf(d0) + fabsf(d1)) + (fabsf(d2) + fabsf(d3));

            // intersection (clamped) + enclosing via width identity (exact)
            float iwu = fminf(px.z, gx1[t]) - fmaxf(px.x, gx0[t]);
            float ihu = fminf(px.w, gy1[t]) - fmaxf(px.y, gy0[t]);
            float iw = fmaxf(iwu, 0.0f), ih = fmaxf(ihu, 0.0f);
            float inter = iw * ih;
            float uni = (a1 + a2[t]) - inter;
            float ew = (pc.z + gb[t].z) - iwu;   // = max-min, always >= 0
            float eh = (pc.w + gb[t].w) - ihu;
            float enc = ew * eh;

            float ru = fast_rcp(uni);
            float re = fast_rcp(enc);

            // cost = 0.25*L1 + (1-prob) - inter/uni - uni/enc
            float base = fmaf(L1, 0.25f, npcol[t][ii * CC]);
            base = fmaf(-uni, re, base);
            float cost = fmaf(-inter, ru, base);
            r[t] = valid[t] ? cost : BIGV;
        }
        reinterpret_cast<float2*>(obase + (size_t)ii * QQ)[0] = res;
    }
}

extern "C" void kernel_launch(void* const* d_in, const int* in_sizes, int n_in,
                              void* d_out, int out_size) {
    const float* pred_logits = (const float*)d_in[0];  // [B,Q,C]
    const float* pred_boxes  = (const float*)d_in[1];  // [B,Q,4]
    const float* boxes       = (const float*)d_in[2];  // [B,Q,4]
    const float* area        = (const float*)d_in[3];  // [B,Q]
    const int*   labels      = (const int*)d_in[4];    // [B,Q]
    float* out = (float*)d_out;                        // [B,Q,Q]

    int rows = BB * QQ;                 // 28800 warps
    int blocks = (rows * 32 + 255) / 256;
    softmax_rows_kernel<<<blocks, 256>>>(pred_logits);

    dim3 grid(QQ / TI, 2, BB);          // (45, 2, 32)
    cost_kernel<<<grid, 256>>>(pred_boxes, boxes, area, labels, out);
}

// round 7
// speedup vs baseline: 1.0711x; 1.0711x over previous
#include <cuda_runtime.h>
#include <cstdint>

// Problem constants (fixed by the reference)
#define BB 32
#define QQ 900
#define CC 92
#define BIGV 100000000.0f
#define TI 20          // i-rows per block (45 blocks in x)
#define J4 (QQ / 4)    // 225 active threads, 4 j's each

typedef unsigned long long u64;

// Scratch: softmax stores (1 - prob).
__device__ float g_nprobs[BB * QQ * CC];

__device__ __forceinline__ float fast_rcp(float x) {
    float r;
    asm("rcp.approx.ftz.f32 %0, %1;" : "=f"(r) : "f"(x));
    return r;
}
// ---- packed f32x2 helpers (Blackwell FFMA2/FADD2/FMUL2 path) ----
__device__ __forceinline__ u64 pk(float x, float y) {
    u64 r; asm("mov.b64 %0, {%1, %2};" : "=l"(r) : "f"(x), "f"(y)); return r;
}
__device__ __forceinline__ float2 upk(u64 v) {
    float2 r; asm("mov.b64 {%0, %1}, %2;" : "=f"(r.x), "=f"(r.y) : "l"(v)); return r;
}
__device__ __forceinline__ u64 add2(u64 a, u64 b) {
    u64 r; asm("add.rn.f32x2 %0, %1, %2;" : "=l"(r) : "l"(a), "l"(b)); return r;
}
__device__ __forceinline__ u64 mul2(u64 a, u64 b) {
    u64 r; asm("mul.rn.f32x2 %0, %1, %2;" : "=l"(r) : "l"(a), "l"(b)); return r;
}
__device__ __forceinline__ u64 fma2(u64 a, u64 b, u64 c) {
    u64 r; asm("fma.rn.f32x2 %0, %1, %2, %3;" : "=l"(r) : "l"(a), "l"(b), "l"(c)); return r;
}

// ---------------------------------------------------------------------------
// Kernel 1: row softmax, stores (1 - p). One warp per (b,i) row of 92 logits.
// ---------------------------------------------------------------------------
__global__ void softmax_rows_kernel(const float* __restrict__ logits) {
    int gwarp = (blockIdx.x * blockDim.x + threadIdx.x) >> 5;
    int lane  = threadIdx.x & 31;
    if (gwarp >= BB * QQ) return;

    const float* in = logits + (size_t)gwarp * CC;
    float v0 = in[lane];
    float v1 = in[lane + 32];
    bool has2 = lane < (CC - 64);
    float v2 = has2 ? in[lane + 64] : -1e30f;

    float m = fmaxf(fmaxf(v0, v1), v2);
    #pragma unroll
    for (int o = 16; o > 0; o >>= 1)
        m = fmaxf(m, __shfl_xor_sync(0xFFFFFFFFu, m, o));

    float e0 = __expf(v0 - m);
    float e1 = __expf(v1 - m);
    float e2 = has2 ? __expf(v2 - m) : 0.0f;
    float s = e0 + e1 + e2;
    #pragma unroll
    for (int o = 16; o > 0; o >>= 1)
        s += __shfl_xor_sync(0xFFFFFFFFu, s, o);

    float inv = __fdividef(1.0f, s);
    float* outp = g_nprobs + (size_t)gwarp * CC;
    outp[lane]      = fmaf(e0, -inv, 1.0f);
    outp[lane + 32] = fmaf(e1, -inv, 1.0f);
    if (has2) outp[lane + 64] = fmaf(e2, -inv, 1.0f);
}

// ---------------------------------------------------------------------------
// Kernel 2: cost matrix, packed-f32x2 arithmetic.
// Block = (i-tile TI, batch). Thread owns 4 j = 2 packed pairs; STG.128 out.
//   cost = 0.25*L1 + (1 - prob) - inter/uni - uni/enc
// ---------------------------------------------------------------------------
__global__ __launch_bounds__(256)
void cost_kernel(const float* __restrict__ pred_boxes,
                 const float* __restrict__ boxes,
                 const float* __restrict__ area,
                 const int*   __restrict__ labels,
                 float* __restrict__ out) {
    const int b   = blockIdx.y;
    const int i0  = blockIdx.x * TI;
    const int tid = threadIdx.x;

    __shared__ float s_np[TI][CC];   // (1 - prob) rows
    __shared__ u64   s_cd[TI][4];    // splat {c,c} of pred cxcywh comps
    __shared__ float4 s_x[TI];       // pred xyxy (scalar use in FMNMX)
    __shared__ u64   s_a1d[TI];      // splat {a1,a1}

    for (int k = tid; k < TI * CC; k += 256) {
        int ii = k / CC;
        int c  = k - ii * CC;
        s_np[ii][c] = g_nprobs[((size_t)(b * QQ + i0 + ii)) * CC + c];
    }
    if (tid < TI) {
        float4 pb = reinterpret_cast<const float4*>(pred_boxes)[b * QQ + i0 + tid];
        s_cd[tid][0] = pk(pb.x, pb.x);
        s_cd[tid][1] = pk(pb.y, pb.y);
        s_cd[tid][2] = pk(pb.z, pb.z);
        s_cd[tid][3] = pk(pb.w, pb.w);
        s_x[tid] = make_float4(pb.x - 0.5f * pb.z, pb.y - 0.5f * pb.w,
                               pb.x + 0.5f * pb.z, pb.y + 0.5f * pb.w);
        float a1 = pb.z * pb.w;
        s_a1d[tid] = pk(a1, a1);
    }
    __syncthreads();

    if (tid >= J4) return;
    const int j0 = tid * 4;

    const u64 NEG1 = pk(-1.0f, -1.0f);
    const u64 QTR  = pk(0.25f, 0.25f);
    const u64 ABSM = 0x7fffffff7fffffffULL;

    // Per-pair packed invariants (pair p covers j0+2p, j0+2p+1)
    u64 ngbx[2], ngby[2], gzp[2], gwp[2], a2p[2];
    float gx0[4], gx1[4], gy0[4], gy1[4];
    int   lab[4];
    bool  valid[4];
    #pragma unroll
    for (int p = 0; p < 2; p++) {
        float4 g0 = reinterpret_cast<const float4*>(boxes)[b * QQ + j0 + 2*p];
        float4 g1 = reinterpret_cast<const float4*>(boxes)[b * QQ + j0 + 2*p + 1];
        ngbx[p] = pk(-g0.x, -g1.x);
        ngby[p] = pk(-g0.y, -g1.y);
        gzp[p]  = pk(g0.z, g1.z);
        gwp[p]  = pk(g0.w, g1.w);
        a2p[p]  = pk(g0.z * g0.w, g1.z * g1.w);
        gx0[2*p]   = g0.x - 0.5f * g0.z; gx1[2*p]   = g0.x + 0.5f * g0.z;
        gy0[2*p]   = g0.y - 0.5f * g0.w; gy1[2*p]   = g0.y + 0.5f * g0.w;
        gx0[2*p+1] = g1.x - 0.5f * g1.z; gx1[2*p+1] = g1.x + 0.5f * g1.z;
        gy0[2*p+1] = g1.y - 0.5f * g1.w; gy1[2*p+1] = g1.y + 0.5f * g1.w;
    }
    #pragma unroll
    for (int t = 0; t < 4; t++) {
        lab[t]   = labels[b * QQ + j0 + t];
        valid[t] = area[b * QQ + j0 + t] > 0.0f;
    }

    float* obase = out + ((size_t)(b * QQ + i0)) * QQ + j0;

    #pragma unroll 4
    for (int ii = 0; ii < TI; ii++) {
        u64 cx = s_cd[ii][0], cy = s_cd[ii][1], cz = s_cd[ii][2], cw = s_cd[ii][3];
        float4 px = s_x[ii];
        u64 a1d = s_a1d[ii];
        const float* nprow = &s_np[ii][0];

        float4 res;
        float* r = &res.x;
        #pragma unroll
        for (int p = 0; p < 2; p++) {
            const int t0 = 2*p, t1 = 2*p + 1;
            // L1 term: diffs packed; abs via LOP3 masks
            u64 d0 = add2(cx, ngbx[p]);
            u64 d1 = add2(cy, ngby[p]);
            u64 d2 = fma2(gzp[p], NEG1, cz);     // pc.z - gb.z
            u64 d3 = fma2(gwp[p], NEG1, cw);
            u64 L1 = add2(add2(d0 & ABSM, d1 & ABSM), add2(d2 & ABSM, d3 & ABSM));

            // intersection: scalar FMNMX (neg folded as modifiers), packed sub
            float mzx0 = fminf(px.z, gx1[t0]),  mzx1 = fminf(px.z, gx1[t1]);
            float nmx0 = fminf(-px.x, -gx0[t0]), nmx1 = fminf(-px.x, -gx0[t1]); // = -max
            u64 iwu = add2(pk(mzx0, mzx1), pk(nmx0, nmx1));
            float mzy0 = fminf(px.w, gy1[t0]),  mzy1 = fminf(px.w, gy1[t1]);
            float nmy0 = fminf(-px.y, -gy0[t0]), nmy1 = fminf(-px.y, -gy0[t1]);
            u64 ihu = add2(pk(mzy0, mzy1), pk(nmy0, nmy1));

            float2 iwuf = upk(iwu), ihuf = upk(ihu);
            u64 iwp = pk(fmaxf(iwuf.x, 0.0f), fmaxf(iwuf.y, 0.0f));
            u64 ihp = pk(fmaxf(ihuf.x, 0.0f), fmaxf(ihuf.y, 0.0f));
            u64 inter = mul2(iwp, ihp);
            u64 uni = fma2(inter, NEG1, add2(a1d, a2p[p]));   // a1+a2-inter

            // enclosing box via width identity: ew = (pc.z+gb.z) - iwu
            u64 ew = fma2(iwu, NEG1, add2(cz, gzp[p]));
            u64 eh = fma2(ihu, NEG1, add2(cw, gwp[p]));
            u64 enc = mul2(ew, eh);

            float2 uf = upk(uni), ef = upk(enc);
            u64 nru = pk(fast_rcp(-uf.x), fast_rcp(-uf.y));   // -1/uni
            u64 nre = pk(fast_rcp(-ef.x), fast_rcp(-ef.y));   // -1/enc

            u64 npp = pk(nprow[lab[t0]], nprow[lab[t1]]);
            u64 base = fma2(L1, QTR, npp);
            base = fma2(uni, nre, base);                      // - uni/enc
            u64 cost = fma2(inter, nru, base);                // - inter/uni
            float2 cf = upk(cost);
            r[t0] = valid[t0] ? cf.x : BIGV;
            r[t1] = valid[t1] ? cf.y : BIGV;
        }
        reinterpret_cast<float4*>(obase + (size_t)ii * QQ)[0] = res;
    }
}

extern "C" void kernel_launch(void* const* d_in, const int* in_sizes, int n_in,
                              void* d_out, int out_size) {
    const float* pred_logits = (const float*)d_in[0];  // [B,Q,C]
    const float* pred_boxes  = (const float*)d_in[1];  // [B,Q,4]
    const float* boxes       = (const float*)d_in[2];  // [B,Q,4]
    const float* area        = (const float*)d_in[3];  // [B,Q]
    const int*   labels      = (const int*)d_in[4];    // [B,Q]
    float* out = (float*)d_out;                        // [B,Q,Q]

    int rows = BB * QQ;
    int blocks = (rows * 32 + 255) / 256;
    softmax_rows_kernel<<<blocks, 256>>>(pred_logits);

    dim3 grid(QQ / TI, BB);             // (45, 32)
    cost_kernel<<<grid, 256>>>(pred_boxes, boxes, area, labels, out);
}

// round 8
// speedup vs baseline: 1.1200x; 1.0456x over previous
#include <cuda_runtime.h>
#include <cstdint>

// Problem constants (fixed by the reference)
#define BB 32
#define QQ 900
#define CC 92
#define BIGV 100000000.0f
#define TI 25          // i-rows per block -> grid.x = 36, 1152 blocks ~ 2 waves
#define J4 (QQ / 4)    // 225 active threads, 4 j's each

// Scratch: softmax stores (1 - prob) for FFMA folding in the cost kernel.
__device__ float g_nprobs[BB * QQ * CC];

__device__ __forceinline__ float fast_rcp(float x) {
    float r;
    asm("rcp.approx.ftz.f32 %0, %1;" : "=f"(r) : "f"(x));
    return r;
}

// ---------------------------------------------------------------------------
// Kernel 1: row softmax, stores (1 - p). One warp per (b,i) row of 92 logits.
// ---------------------------------------------------------------------------
__global__ void softmax_rows_kernel(const float* __restrict__ logits) {
    int gwarp = (blockIdx.x * blockDim.x + threadIdx.x) >> 5;
    int lane  = threadIdx.x & 31;
    if (gwarp >= BB * QQ) return;

    const float* in = logits + (size_t)gwarp * CC;
    float v0 = in[lane];
    float v1 = in[lane + 32];
    bool has2 = lane < (CC - 64);          // lane < 28
    float v2 = has2 ? in[lane + 64] : -1e30f;

    float m = fmaxf(fmaxf(v0, v1), v2);
    #pragma unroll
    for (int o = 16; o > 0; o >>= 1)
        m = fmaxf(m, __shfl_xor_sync(0xFFFFFFFFu, m, o));

    float e0 = __expf(v0 - m);
    float e1 = __expf(v1 - m);
    float e2 = has2 ? __expf(v2 - m) : 0.0f;
    float s = e0 + e1 + e2;
    #pragma unroll
    for (int o = 16; o > 0; o >>= 1)
        s += __shfl_xor_sync(0xFFFFFFFFu, s, o);

    float inv = __fdividef(1.0f, s);
    float* outp = g_nprobs + (size_t)gwarp * CC;
    outp[lane]      = fmaf(e0, -inv, 1.0f);
    outp[lane + 32] = fmaf(e1, -inv, 1.0f);
    if (has2) outp[lane + 64] = fmaf(e2, -inv, 1.0f);
}

// ---------------------------------------------------------------------------
// Kernel 2: cost matrix. Block = (i-tile of TI rows, batch b).
// Each thread owns 4 consecutive j and emits TI float4 (STG.128) stores.
//   cost = 0.25*L1 + (1 - prob) - inter/uni - uni/enc
//   enc width via exact identity: ew = pw + gw - iw_unclamped
// ---------------------------------------------------------------------------
__global__ __launch_bounds__(256)
void cost_kernel(const float* __restrict__ pred_boxes,
                 const float* __restrict__ boxes,
                 const float* __restrict__ area,
                 const int*   __restrict__ labels,
                 float* __restrict__ out) {
    const int b  = blockIdx.y;
    const int i0 = blockIdx.x * TI;
    const int tid = threadIdx.x;

    __shared__ float  s_np[TI][CC];     // (1 - prob) rows for the i-tile
    __shared__ float4 s_c[TI];          // pred box cxcywh
    __shared__ float4 s_x[TI];          // pred box xyxy
    __shared__ float  s_a1[TI];         // pred box area (w*h)

    for (int k = tid; k < TI * CC; k += 256) {
        int ii = k / CC;
        int c  = k - ii * CC;
        s_np[ii][c] = g_nprobs[((size_t)(b * QQ + i0 + ii)) * CC + c];
    }
    if (tid < TI) {
        float4 pb = reinterpret_cast<const float4*>(pred_boxes)[b * QQ + i0 + tid];
        s_c[tid] = pb;
        s_x[tid] = make_float4(pb.x - 0.5f * pb.z, pb.y - 0.5f * pb.w,
                               pb.x + 0.5f * pb.z, pb.y + 0.5f * pb.w);
        s_a1[tid] = pb.z * pb.w;
    }
    __syncthreads();

    if (tid >= J4) return;              // 225 active threads cover j=0..899
    const int j0 = tid * 4;

    float4 gb[4];
    float gx0[4], gy0[4], gx1[4], gy1[4], a2[4];
    bool  valid[4];
    const float* npcol[4];              // &s_np[0][lab[t]]
    #pragma unroll
    for (int t = 0; t < 4; t++) {
        gb[t] = reinterpret_cast<const float4*>(boxes)[b * QQ + j0 + t];
        int lab = labels[b * QQ + j0 + t];
        npcol[t] = &s_np[0][lab];
        valid[t] = area[b * QQ + j0 + t] > 0.0f;
        gx0[t] = gb[t].x - 0.5f * gb[t].z; gy0[t] = gb[t].y - 0.5f * gb[t].w;
        gx1[t] = gb[t].x + 0.5f * gb[t].z; gy1[t] = gb[t].y + 0.5f * gb[t].w;
        a2[t]  = gb[t].z * gb[t].w;
    }

    float* obase = out + ((size_t)(b * QQ + i0)) * QQ + j0;

    #pragma unroll 5
    for (int ii = 0; ii < TI; ii++) {
        float4 pc = s_c[ii];
        float4 px = s_x[ii];
        float  a1 = s_a1[ii];
        float4 res;
        float* r = &res.x;
        #pragma unroll
        for (int t = 0; t < 4; t++) {
            // mean-L1 (x0.25 folded into final FFMA)
            float d0 = pc.x - gb[t].x, d1 = pc.y - gb[t].y;
            float d2 = pc.z - gb[t].z, d3 = pc.w - gb[t].w;
            float L1 = (fabsf(d0) + fabsf(d1)) + (fabsf(d2) + fabsf(d3));

            // intersection (clamped) + enclosing via width identity (exact)
            float iwu = fminf(px.z, gx1[t]) - fmaxf(px.x, gx0[t]);
            float ihu = fminf(px.w, gy1[t]) - fmaxf(px.y, gy0[t]);
            float iw = fmaxf(iwu, 0.0f), ih = fmaxf(ihu, 0.0f);
            float inter = iw * ih;
            float uni = (a1 + a2[t]) - inter;
            float ew = (pc.z + gb[t].z) - iwu;   // = max-min, always >= 0
            float eh = (pc.w + gb[t].w) - ihu;
            float enc = ew * eh;

            float ru = fast_rcp(uni);
            float re = fast_rcp(enc);

            // cost = 0.25*L1 + (1-prob) - inter/uni - uni/enc
            float base = fmaf(L1, 0.25f, npcol[t][ii * CC]);
            base = fmaf(-uni, re, base);
            float cost = fmaf(-inter, ru, base);
            r[t] = valid[t] ? cost : BIGV;
        }
        reinterpret_cast<float4*>(obase + (size_t)ii * QQ)[0] = res;
    }
}

extern "C" void kernel_launch(void* const* d_in, const int* in_sizes, int n_in,
                              void* d_out, int out_size) {
    const float* pred_logits = (const float*)d_in[0];  // [B,Q,C]
    const float* pred_boxes  = (const float*)d_in[1];  // [B,Q,4]
    const float* boxes       = (const float*)d_in[2];  // [B,Q,4]
    const float* area        = (const float*)d_in[3];  // [B,Q]
    const int*   labels      = (const int*)d_in[4];    // [B,Q]
    float* out = (float*)d_out;                        // [B,Q,Q]

    int rows = BB * QQ;                 // 28800 warps
    int blocks = (rows * 32 + 255) / 256;
    softmax_rows_kernel<<<blocks, 256>>>(pred_logits);

    dim3 grid(QQ / TI, BB);             // (36, 32) = 1152 blocks ~ 2 waves
    cost_kernel<<<grid, 256>>>(pred_boxes, boxes, area, labels, out);
}

// round 10
// speedup vs baseline: 1.2709x; 1.1348x over previous
#include <cuda_runtime.h>
#include <cstdint>

// Problem constants (fixed by the reference)
#define BB 32
#define QQ 900
#define CC 92
#define BIGV 100000000.0f
#define TI 25          // i-rows per block -> grid.x = 36, 1152 blocks ~ 2 waves
#define J4 (QQ / 4)    // 225 active threads, 4 j's each

__device__ __forceinline__ float fast_rcp(float x) {
    float r;
    asm("rcp.approx.ftz.f32 %0, %1;" : "=f"(r) : "f"(x));
    return r;
}

// ---------------------------------------------------------------------------
// Fused kernel: per-block softmax of its TI rows (warp-per-row) directly into
// shared, then the cost matrix body.
//   cost = 0.25*L1 + (1 - prob) - inter/uni - uni/enc
// ---------------------------------------------------------------------------
__global__ __launch_bounds__(256)
void cost_kernel(const float* __restrict__ pred_logits,
                 const float* __restrict__ pred_boxes,
                 const float* __restrict__ boxes,
                 const float* __restrict__ area,
                 const int*   __restrict__ labels,
                 float* __restrict__ out) {
    const int b  = blockIdx.y;
    const int i0 = blockIdx.x * TI;
    const int tid = threadIdx.x;
    const int wid = tid >> 5;
    const int lane = tid & 31;

    __shared__ float  s_np[TI][CC];     // (1 - prob) rows for the i-tile
    __shared__ float4 s_c[TI];          // pred box cxcywh
    __shared__ float4 s_x[TI];          // pred box xyxy
    __shared__ float  s_a1[TI];         // pred box area (w*h)

    // ---- fused softmax: warp w handles rows w, w+8, w+16, ... ----
    for (int row = wid; row < TI; row += 8) {
        const float* in = pred_logits + ((size_t)(b * QQ + i0 + row)) * CC;
        float v0 = in[lane];
        float v1 = in[lane + 32];
        bool has2 = lane < (CC - 64);          // lane < 28
        float v2 = has2 ? in[lane + 64] : -1e30f;

        float m = fmaxf(fmaxf(v0, v1), v2);
        #pragma unroll
        for (int o = 16; o > 0; o >>= 1)
            m = fmaxf(m, __shfl_xor_sync(0xFFFFFFFFu, m, o));

        float e0 = __expf(v0 - m);
        float e1 = __expf(v1 - m);
        float e2 = has2 ? __expf(v2 - m) : 0.0f;
        float s = e0 + e1 + e2;
        #pragma unroll
        for (int o = 16; o > 0; o >>= 1)
            s += __shfl_xor_sync(0xFFFFFFFFu, s, o);

        float inv = __fdividef(1.0f, s);
        s_np[row][lane]      = fmaf(e0, -inv, 1.0f);
        s_np[row][lane + 32] = fmaf(e1, -inv, 1.0f);
        if (has2) s_np[row][lane + 64] = fmaf(e2, -inv, 1.0f);
    }
    // ---- per-i box precomputes ----
    if (tid < TI) {
        float4 pb = reinterpret_cast<const float4*>(pred_boxes)[b * QQ + i0 + tid];
        s_c[tid] = pb;
        s_x[tid] = make_float4(pb.x - 0.5f * pb.z, pb.y - 0.5f * pb.w,
                               pb.x + 0.5f * pb.z, pb.y + 0.5f * pb.w);
        s_a1[tid] = pb.z * pb.w;
    }
    __syncthreads();

    if (tid >= J4) return;              // 225 active threads cover j=0..899
    const int j0 = tid * 4;

    float4 gb[4];
    float gx0[4], gy0[4], gx1[4], gy1[4], a2[4];
    bool  valid[4];
    const float* npcol[4];              // &s_np[0][lab[t]]
    #pragma unroll
    for (int t = 0; t < 4; t++) {
        gb[t] = reinterpret_cast<const float4*>(boxes)[b * QQ + j0 + t];
        int lab = labels[b * QQ + j0 + t];
        npcol[t] = &s_np[0][lab];
        valid[t] = area[b * QQ + j0 + t] > 0.0f;
        gx0[t] = gb[t].x - 0.5f * gb[t].z; gy0[t] = gb[t].y - 0.5f * gb[t].w;
        gx1[t] = gb[t].x + 0.5f * gb[t].z; gy1[t] = gb[t].y + 0.5f * gb[t].w;
        a2[t]  = gb[t].z * gb[t].w;
    }

    float* obase = out + ((size_t)(b * QQ + i0)) * QQ + j0;

    #pragma unroll 5
    for (int ii = 0; ii < TI; ii++) {
        float4 pc = s_c[ii];
        float4 px = s_x[ii];
        float  a1 = s_a1[ii];
        float4 res;
        float* r = &res.x;
        #pragma unroll
        for (int t = 0; t < 4; t++) {
            // mean-L1 (x0.25 folded into final FFMA)
            float d0 = pc.x - gb[t].x, d1 = pc.y - gb[t].y;
            float d2 = pc.z - gb[t].z, d3 = pc.w - gb[t].w;
            float L1 = (fabsf(d0) + fabsf(d1)) + (fabsf(d2) + fabsf(d3));

            // intersection (clamped) + enclosing via width identity (exact)
            float iwu = fminf(px.z, gx1[t]) - fmaxf(px.x, gx0[t]);
            float ihu = fminf(px.w, gy1[t]) - fmaxf(px.y, gy0[t]);
            float iw = fmaxf(iwu, 0.0f), ih = fmaxf(ihu, 0.0f);
            float inter = iw * ih;
            float uni = (a1 + a2[t]) - inter;
            float ew = (pc.z + gb[t].z) - iwu;   // = max-min, always >= 0
            float eh = (pc.w + gb[t].w) - ihu;
            float enc = ew * eh;

            float ru = fast_rcp(uni);
            float re = fast_rcp(enc);

            // cost = 0.25*L1 + (1-prob) - inter/uni - uni/enc
            float base = fmaf(L1, 0.25f, npcol[t][ii * CC]);
            base = fmaf(-uni, re, base);
            float cost = fmaf(-inter, ru, base);
            r[t] = valid[t] ? cost : BIGV;
        }
        reinterpret_cast<float4*>(obase + (size_t)ii * QQ)[0] = res;
    }
}

extern "C" void kernel_launch(void* const* d_in, const int* in_sizes, int n_in,
                              void* d_out, int out_size) {
    const float* pred_logits = (const float*)d_in[0];  // [B,Q,C]
    const float* pred_boxes  = (const float*)d_in[1];  // [B,Q,4]
    const float* boxes       = (const float*)d_in[2];  // [B,Q,4]
    const float* area        = (const float*)d_in[3];  // [B,Q]
    const int*   labels      = (const int*)d_in[4];    // [B,Q]
    float* out = (float*)d_out;                        // [B,Q,Q]

    dim3 grid(QQ / TI, BB);             // (36, 32) = 1152 blocks ~ 2 waves
    cost_kernel<<<grid, 256>>>(pred_logits, pred_boxes, boxes, area, labels, out);
}

// round 12
// speedup vs baseline: 1.2727x; 1.0014x over previous
#include <cuda_runtime.h>
#include <cstdint>

// Problem constants (fixed by the reference)
#define BB 32
#define QQ 900
#define CC 92
#define BIGV 100000000.0f
#define TI 25          // i-rows per block -> grid.x = 36, 1152 blocks ~ 2 waves
#define J4 (QQ / 4)    // 225 active threads, 4 j's each
#define NPST 28        // padded ii-stride of transposed prob table (16B rows)

__device__ __forceinline__ float fast_rcp(float x) {
    float r;
    asm("rcp.approx.ftz.f32 %0, %1;" : "=f"(r) : "f"(x));
    return r;
}
__device__ __forceinline__ float f4c(const float4& v, int k) {
    switch (k) { case 0: return v.x; case 1: return v.y; case 2: return v.z; default: return v.w; }
}

// ---------------------------------------------------------------------------
// Fused kernel: per-block softmax into a TRANSPOSED (1-p) table, then the
// cost body in midpoint form with the CORRECT interval identities:
//   overlap_unclamped = (hp + hg) - max(|dc|, |dh|)
//   enclose           = (hp + hg) + max(|dc|, |dh|)
//   cost = 0.25u + 0.5v + (1 - prob) - inter/uni - uni/enc
// where u = |dcx|+|dcy|, v = |dhx|+|dhy| (half-extent diffs; |dw| = 2|dhx|).
// ---------------------------------------------------------------------------
__global__ __launch_bounds__(256)
void cost_kernel(const float* __restrict__ pred_logits,
                 const float* __restrict__ pred_boxes,
                 const float* __restrict__ boxes,
                 const float* __restrict__ area,
                 const int*   __restrict__ labels,
                 float* __restrict__ out) {
    const int b  = blockIdx.y;
    const int i0 = blockIdx.x * TI;
    const int tid = threadIdx.x;
    const int wid = tid >> 5;
    const int lane = tid & 31;

    __shared__ float  s_npT[CC][NPST];  // (1 - prob), transposed: [class][ii]
    __shared__ float4 s_cb[TI];         // pred box (cx, cy, w/2, h/2)
    __shared__ float  s_a1[TI];         // pred box area w*h

    // ---- fused softmax (warp-per-row), write transposed ----
    for (int row = wid; row < TI; row += 8) {
        const float* in = pred_logits + ((size_t)(b * QQ + i0 + row)) * CC;
        float v0 = in[lane];
        float v1 = in[lane + 32];
        bool has2 = lane < (CC - 64);          // lane < 28
        float v2 = has2 ? in[lane + 64] : -1e30f;

        float m = fmaxf(fmaxf(v0, v1), v2);
        #pragma unroll
        for (int o = 16; o > 0; o >>= 1)
            m = fmaxf(m, __shfl_xor_sync(0xFFFFFFFFu, m, o));

        float e0 = __expf(v0 - m);
        float e1 = __expf(v1 - m);
        float e2 = has2 ? __expf(v2 - m) : 0.0f;
        float s = e0 + e1 + e2;
        #pragma unroll
        for (int o = 16; o > 0; o >>= 1)
            s += __shfl_xor_sync(0xFFFFFFFFu, s, o);

        float inv = __fdividef(1.0f, s);
        s_npT[lane][row]      = fmaf(e0, -inv, 1.0f);
        s_npT[lane + 32][row] = fmaf(e1, -inv, 1.0f);
        if (has2) s_npT[lane + 64][row] = fmaf(e2, -inv, 1.0f);
    }
    // ---- per-i box precomputes ----
    if (tid < TI) {
        float4 pb = reinterpret_cast<const float4*>(pred_boxes)[b * QQ + i0 + tid];
        s_cb[tid] = make_float4(pb.x, pb.y, 0.5f * pb.z, 0.5f * pb.w);
        s_a1[tid] = pb.z * pb.w;
    }
    __syncthreads();

    if (tid >= J4) return;              // 225 active threads cover j=0..899
    const int j0 = tid * 4;

    float gcx[4], gcy[4], hgz[4], hgw[4], a2[4];
    bool  valid[4];
    const float* npp[4];                // &s_npT[lab[t]][0]
    #pragma unroll
    for (int t = 0; t < 4; t++) {
        float4 g = reinterpret_cast<const float4*>(boxes)[b * QQ + j0 + t];
        gcx[t] = g.x; gcy[t] = g.y;
        hgz[t] = 0.5f * g.z; hgw[t] = 0.5f * g.w;
        a2[t]  = g.z * g.w;
        npp[t] = &s_npT[labels[b * QQ + j0 + t]][0];
        valid[t] = area[b * QQ + j0 + t] > 0.0f;
    }

    float* obase = out + ((size_t)(b * QQ + i0)) * QQ + j0;

    // ---- main: 6 groups of 4 ii (np via LDS.128), then remainder ii=24 ----
    #pragma unroll 2
    for (int g = 0; g < 6; g++) {
        float4 np4[4];
        #pragma unroll
        for (int t = 0; t < 4; t++)
            np4[t] = *reinterpret_cast<const float4*>(npp[t] + 4 * g);

        #pragma unroll
        for (int k = 0; k < 4; k++) {
            const int ii = 4 * g + k;
            float4 pc = s_cb[ii];
            float  a1 = s_a1[ii];
            float4 res;
            float* r = &res.x;
            #pragma unroll
            for (int t = 0; t < 4; t++) {
                float d0 = pc.x - gcx[t], d1 = pc.y - gcy[t];
                float d2 = pc.z - hgz[t], d3 = pc.w - hgw[t];
                float u = fabsf(d0) + fabsf(d1);      // center L1
                float v = fabsf(d2) + fabsf(d3);      // half-extent L1
                float mx = fmaxf(fabsf(d0), fabsf(d2));
                float my = fmaxf(fabsf(d1), fabsf(d3));
                float sz = pc.z + hgz[t], sw = pc.w + hgw[t];
                float iwu = sz - mx, ihu = sw - my;
                float ew  = sz + mx, eh  = sw + my;
                float iw = fmaxf(iwu, 0.0f), ih = fmaxf(ihu, 0.0f);
                float inter = iw * ih;
                float enc   = ew * eh;
                float uni   = (a1 + a2[t]) - inter;
                float ru = fast_rcp(uni);
                float re = fast_rcp(enc);
                float base = fmaf(v, 0.5f, f4c(np4[t], k));
                base = fmaf(u, 0.25f, base);
                base = fmaf(-uni, re, base);
                float cost = fmaf(-inter, ru, base);
                r[t] = valid[t] ? cost : BIGV;
            }
            reinterpret_cast<float4*>(obase + (size_t)ii * QQ)[0] = res;
        }
    }
    { // remainder ii = 24
        const int ii = 24;
        float4 pc = s_cb[ii];
        float  a1 = s_a1[ii];
        float4 res;
        float* r = &res.x;
        #pragma unroll
        for (int t = 0; t < 4; t++) {
            float np = npp[t][ii];
            float d0 = pc.x - gcx[t], d1 = pc.y - gcy[t];
            float d2 = pc.z - hgz[t], d3 = pc.w - hgw[t];
            float u = fabsf(d0) + fabsf(d1);
            float v = fabsf(d2) + fabsf(d3);
            float mx = fmaxf(fabsf(d0), fabsf(d2));
            float my = fmaxf(fabsf(d1), fabsf(d3));
            float sz = pc.z + hgz[t], sw = pc.w + hgw[t];
            float iwu = sz - mx, ihu = sw - my;
            float ew  = sz + mx, eh  = sw + my;
            float iw = fmaxf(iwu, 0.0f), ih = fmaxf(ihu, 0.0f);
            float inter = iw * ih;
            float enc   = ew * eh;
            float uni   = (a1 + a2[t]) - inter;
            float ru = fast_rcp(uni);
            float re = fast_rcp(enc);
            float base = fmaf(v, 0.5f, np);
            base = fmaf(u, 0.25f, base);
            base = fmaf(-uni, re, base);
            float cost = fmaf(-inter, ru, base);
            r[t] = valid[t] ? cost : BIGV;
        }
        reinterpret_cast<float4*>(obase + (size_t)ii * QQ)[0] = res;
    }
}

extern "C" void kernel_launch(void* const* d_in, const int* in_sizes, int n_in,
                              void* d_out, int out_size) {
    const float* pred_logits = (const float*)d_in[0];  // [B,Q,C]
    const float* pred_boxes  = (const float*)d_in[1];  // [B,Q,4]
    const float* boxes       = (const float*)d_in[2];  // [B,Q,4]
    const float* area        = (const float*)d_in[3];  // [B,Q]
    const int*   labels      = (const int*)d_in[4];    // [B,Q]
    float* out = (float*)d_out;                        // [B,Q,Q]

    dim3 grid(QQ / TI, BB);             // (36, 32) = 1152 blocks ~ 2 waves
    cost_kernel<<<grid, 256>>>(pred_logits, pred_boxes, boxes, area, labels, out);
}

// round 14
// speedup vs baseline: 1.3333x; 1.0476x over previous
#include <cuda_runtime.h>
#include <cstdint>

// Problem constants (fixed by the reference)
#define BB 32
#define QQ 900
#define CC 92
#define BIGV 100000000.0f
#define TI 25          // i-rows per block -> grid.x = 36, 1152 blocks ~ 2 waves
#define J4 (QQ / 4)    // 225 active threads, 4 j's each
#define NPST 28        // padded ii-stride of transposed prob table

__device__ __forceinline__ float fast_rcp(float x) {
    float r;
    asm("rcp.approx.ftz.f32 %0, %1;" : "=f"(r) : "f"(x));
    return r;
}

// ---------------------------------------------------------------------------
// Fused kernel: per-block softmax into a TRANSPOSED (1-p) table, then the
// cost body in midpoint form:
//   overlap_unclamped = (hp + hg) - max(|dc|, |dh|)
//   enclose           = (hp + hg) + max(|dc|, |dh|)
//   cost = 0.25u + 0.5v + (1 - prob) - inter/uni - uni/enc
// ---------------------------------------------------------------------------
__global__ __launch_bounds__(256, 4)
void cost_kernel(const float* __restrict__ pred_logits,
                 const float* __restrict__ pred_boxes,
                 const float* __restrict__ boxes,
                 const float* __restrict__ area,
                 const int*   __restrict__ labels,
                 float* __restrict__ out) {
    const int b  = blockIdx.y;
    const int i0 = blockIdx.x * TI;
    const int tid = threadIdx.x;
    const int wid = tid >> 5;
    const int lane = tid & 31;

    __shared__ float  s_npT[CC][NPST];  // (1 - prob), transposed: [class][ii]
    __shared__ float4 s_cb[TI];         // pred box (cx, cy, w/2, h/2)
    __shared__ float  s_a1[TI];         // pred box area w*h

    // ---- fused softmax (warp-per-row), write transposed ----
    for (int row = wid; row < TI; row += 8) {
        const float* in = pred_logits + ((size_t)(b * QQ + i0 + row)) * CC;
        float v0 = in[lane];
        float v1 = in[lane + 32];
        bool has2 = lane < (CC - 64);          // lane < 28
        float v2 = has2 ? in[lane + 64] : -1e30f;

        float m = fmaxf(fmaxf(v0, v1), v2);
        #pragma unroll
        for (int o = 16; o > 0; o >>= 1)
            m = fmaxf(m, __shfl_xor_sync(0xFFFFFFFFu, m, o));

        float e0 = __expf(v0 - m);
        float e1 = __expf(v1 - m);
        float e2 = has2 ? __expf(v2 - m) : 0.0f;
        float s = e0 + e1 + e2;
        #pragma unroll
        for (int o = 16; o > 0; o >>= 1)
            s += __shfl_xor_sync(0xFFFFFFFFu, s, o);

        float inv = __fdividef(1.0f, s);
        s_npT[lane][row]      = fmaf(e0, -inv, 1.0f);
        s_npT[lane + 32][row] = fmaf(e1, -inv, 1.0f);
        if (has2) s_npT[lane + 64][row] = fmaf(e2, -inv, 1.0f);
    }
    // ---- per-i box precomputes ----
    if (tid < TI) {
        float4 pb = reinterpret_cast<const float4*>(pred_boxes)[b * QQ + i0 + tid];
        s_cb[tid] = make_float4(pb.x, pb.y, 0.5f * pb.z, 0.5f * pb.w);
        s_a1[tid] = pb.z * pb.w;
    }
    __syncthreads();

    if (tid >= J4) return;              // 225 active threads cover j=0..899
    const int j0 = tid * 4;

    float gcx[4], gcy[4], hgz[4], hgw[4], a2[4];
    bool  valid[4];
    const float* npp[4];                // &s_npT[lab[t]][0]
    #pragma unroll
    for (int t = 0; t < 4; t++) {
        float4 g = reinterpret_cast<const float4*>(boxes)[b * QQ + j0 + t];
        gcx[t] = g.x; gcy[t] = g.y;
        hgz[t] = 0.5f * g.z; hgw[t] = 0.5f * g.w;
        a2[t]  = g.z * g.w;
        npp[t] = &s_npT[labels[b * QQ + j0 + t]][0];
        valid[t] = area[b * QQ + j0 + t] > 0.0f;
    }

    float* obase = out + ((size_t)(b * QQ + i0)) * QQ + j0;

    // ---- main: 12 groups of 2 ii (np via LDS.64), then remainder ii=24 ----
    #pragma unroll 3
    for (int g = 0; g < 12; g++) {
        float2 np2[4];
        #pragma unroll
        for (int t = 0; t < 4; t++)
            np2[t] = *reinterpret_cast<const float2*>(npp[t] + 2 * g);

        #pragma unroll
        for (int k = 0; k < 2; k++) {
            const int ii = 2 * g + k;
            float4 pc = s_cb[ii];
            float  a1 = s_a1[ii];
            float4 res;
            float* r = &res.x;
            #pragma unroll
            for (int t = 0; t < 4; t++) {
                float np = k ? np2[t].y : np2[t].x;
                float d0 = pc.x - gcx[t], d1 = pc.y - gcy[t];
                float d2 = pc.z - hgz[t], d3 = pc.w - hgw[t];
                float u = fabsf(d0) + fabsf(d1);      // center L1
                float v = fabsf(d2) + fabsf(d3);      // half-extent L1
                float mx = fmaxf(fabsf(d0), fabsf(d2));
                float my = fmaxf(fabsf(d1), fabsf(d3));
                float sz = pc.z + hgz[t], sw = pc.w + hgw[t];
                float iwu = sz - mx, ihu = sw - my;
                float ew  = sz + mx, eh  = sw + my;
                float iw = fmaxf(iwu, 0.0f), ih = fmaxf(ihu, 0.0f);
                float inter = iw * ih;
                float enc   = ew * eh;
                float uni   = (a1 + a2[t]) - inter;
                float ru = fast_rcp(uni);
                float re = fast_rcp(enc);
                float base = fmaf(v, 0.5f, np);
                base = fmaf(u, 0.25f, base);
                base = fmaf(-uni, re, base);
                float cost = fmaf(-inter, ru, base);
                r[t] = valid[t] ? cost : BIGV;
            }
            reinterpret_cast<float4*>(obase + (size_t)ii * QQ)[0] = res;
        }
    }
    { // remainder ii = 24
        const int ii = 24;
        float4 pc = s_cb[ii];
        float  a1 = s_a1[ii];
        float4 res;
        float* r = &res.x;
        #pragma unroll
        for (int t = 0; t < 4; t++) {
            float np = npp[t][ii];
            float d0 = pc.x - gcx[t], d1 = pc.y - gcy[t];
            float d2 = pc.z - hgz[t], d3 = pc.w - hgw[t];
            float u = fabsf(d0) + fabsf(d1);
            float v = fabsf(d2) + fabsf(d3);
            float mx = fmaxf(fabsf(d0), fabsf(d2));
            float my = fmaxf(fabsf(d1), fabsf(d3));
            float sz = pc.z + hgz[t], sw = pc.w + hgw[t];
            float iwu = sz - mx, ihu = sw - my;
            float ew  = sz + mx, eh  = sw + my;
            float iw = fmaxf(iwu, 0.0f), ih = fmaxf(ihu, 0.0f);
            float inter = iw * ih;
            float enc   = ew * eh;
            float uni   = (a1 + a2[t]) - inter;
            float ru = fast_rcp(uni);
            float re = fast_rcp(enc);
            float base = fmaf(v, 0.5f, np);
            base = fmaf(u, 0.25f, base);
            base = fmaf(-uni, re, base);
            float cost = fmaf(-inter, ru, base);
            r[t] = valid[t] ? cost : BIGV;
        }
        reinterpret_cast<float4*>(obase + (size_t)ii * QQ)[0] = res;
    }
}

extern "C" void kernel_launch(void* const* d_in, const int* in_sizes, int n_in,
                              void* d_out, int out_size) {
    const float* pred_logits = (const float*)d_in[0];  // [B,Q,C]
    const float* pred_boxes  = (const float*)d_in[1];  // [B,Q,4]
    const float* boxes       = (const float*)d_in[2];  // [B,Q,4]
    const float* area        = (const float*)d_in[3];  // [B,Q]
    const int*   labels      = (const int*)d_in[4];    // [B,Q]
    float* out = (float*)d_out;                        // [B,Q,Q]

    dim3 grid(QQ / TI, BB);             // (36, 32) = 1152 blocks ~ 2 waves
    cost_kernel<<<grid, 256>>>(pred_logits, pred_boxes, boxes, area, labels, out);
}

// round 15
// speedup vs baseline: 1.4121x; 1.0591x over previous
#include <cuda_runtime.h>
#include <cstdint>

// Problem constants (fixed by the reference)
#define BB 32
#define QQ 900
#define CC 92
#define BIGV 100000000.0f
#define TI 25          // i-rows per block -> grid.x = 36, 1152 blocks ~ 2 waves
#define NPST 28        // padded ii-stride of transposed prob table

__device__ __forceinline__ float fast_rcp(float x) {
    float r;
    asm("rcp.approx.ftz.f32 %0, %1;" : "=f"(r) : "f"(x));
    return r;
}

// ---------------------------------------------------------------------------
// Fused kernel: per-block softmax into a TRANSPOSED (1-p) table, then the
// cost body in midpoint form:
//   overlap_unclamped = (hp + hg) - max(|dc|, |dh|)
//   enclose           = (hp + hg) + max(|dc|, |dh|)
//   cost = 0.25u + 0.5v + (1 - prob) - inter/uni - uni/enc
// Warps 0-6 (224 thr x 4 j) cover j=0..895; warp 7 covers the j=896..899
// strip (one row per lane) so no warp issues a mostly-dead stream.
// ---------------------------------------------------------------------------
__global__ __launch_bounds__(256, 4)
void cost_kernel(const float* __restrict__ pred_logits,
                 const float* __restrict__ pred_boxes,
                 const float* __restrict__ boxes,
                 const float* __restrict__ area,
                 const int*   __restrict__ labels,
                 float* __restrict__ out) {
    const int b  = blockIdx.y;
    const int i0 = blockIdx.x * TI;
    const int tid = threadIdx.x;
    const int wid = tid >> 5;
    const int lane = tid & 31;

    __shared__ float  s_npT[CC][NPST];  // (1 - prob), transposed: [class][ii]
    __shared__ float4 s_cb[TI];         // pred box (cx, cy, w/2, h/2)
    __shared__ float  s_a1[TI];         // pred box area w*h

    // ---- fused softmax (warp-per-row), write transposed ----
    for (int row = wid; row < TI; row += 8) {
        const float* in = pred_logits + ((size_t)(b * QQ + i0 + row)) * CC;
        float v0 = in[lane];
        float v1 = in[lane + 32];
        bool has2 = lane < (CC - 64);          // lane < 28
        float v2 = has2 ? in[lane + 64] : -1e30f;

        float m = fmaxf(fmaxf(v0, v1), v2);
        #pragma unroll
        for (int o = 16; o > 0; o >>= 1)
            m = fmaxf(m, __shfl_xor_sync(0xFFFFFFFFu, m, o));

        float e0 = __expf(v0 - m);
        float e1 = __expf(v1 - m);
        float e2 = has2 ? __expf(v2 - m) : 0.0f;
        float s = e0 + e1 + e2;
        #pragma unroll
        for (int o = 16; o > 0; o >>= 1)
            s += __shfl_xor_sync(0xFFFFFFFFu, s, o);

        float inv = __fdividef(1.0f, s);
        s_npT[lane][row]      = fmaf(e0, -inv, 1.0f);
        s_npT[lane + 32][row] = fmaf(e1, -inv, 1.0f);
        if (has2) s_npT[lane + 64][row] = fmaf(e2, -inv, 1.0f);
    }
    // ---- per-i box precomputes ----
    if (tid < TI) {
        float4 pb = reinterpret_cast<const float4*>(pred_boxes)[b * QQ + i0 + tid];
        s_cb[tid] = make_float4(pb.x, pb.y, 0.5f * pb.z, 0.5f * pb.w);
        s_a1[tid] = pb.z * pb.w;
    }
    __syncthreads();

    if (tid < 224) {
        // ==== main path: 224 threads, 4 consecutive j each (j = 0..895) ====
        const int j0 = tid * 4;

        float gcx[4], gcy[4], hgz[4], hgw[4], a2[4];
        bool  valid[4];
        const float* npp[4];                // &s_npT[lab[t]][0]
        #pragma unroll
        for (int t = 0; t < 4; t++) {
            float4 g = reinterpret_cast<const float4*>(boxes)[b * QQ + j0 + t];
            gcx[t] = g.x; gcy[t] = g.y;
            hgz[t] = 0.5f * g.z; hgw[t] = 0.5f * g.w;
            a2[t]  = g.z * g.w;
            npp[t] = &s_npT[labels[b * QQ + j0 + t]][0];
            valid[t] = area[b * QQ + j0 + t] > 0.0f;
        }

        float* obase = out + ((size_t)(b * QQ + i0)) * QQ + j0;

        #pragma unroll 3
        for (int g = 0; g < 12; g++) {
            float2 np2[4];
            #pragma unroll
            for (int t = 0; t < 4; t++)
                np2[t] = *reinterpret_cast<const float2*>(npp[t] + 2 * g);

            #pragma unroll
            for (int k = 0; k < 2; k++) {
                const int ii = 2 * g + k;
                float4 pc = s_cb[ii];
                float  a1 = s_a1[ii];
                float4 res;
                float* r = &res.x;
                #pragma unroll
                for (int t = 0; t < 4; t++) {
                    float np = k ? np2[t].y : np2[t].x;
                    float d0 = pc.x - gcx[t], d1 = pc.y - gcy[t];
                    float d2 = pc.z - hgz[t], d3 = pc.w - hgw[t];
                    float u = fabsf(d0) + fabsf(d1);
                    float v = fabsf(d2) + fabsf(d3);
                    float mx = fmaxf(fabsf(d0), fabsf(d2));
                    float my = fmaxf(fabsf(d1), fabsf(d3));
                    float sz = pc.z + hgz[t], sw = pc.w + hgw[t];
                    float iwu = sz - mx, ihu = sw - my;
                    float ew  = sz + mx, eh  = sw + my;
                    float iw = fmaxf(iwu, 0.0f), ih = fmaxf(ihu, 0.0f);
                    float inter = iw * ih;
                    float enc   = ew * eh;
                    float uni   = (a1 + a2[t]) - inter;
                    float ru = fast_rcp(uni);
                    float re = fast_rcp(enc);
                    float base = fmaf(v, 0.5f, np);
                    base = fmaf(u, 0.25f, base);
                    base = fmaf(-uni, re, base);
                    float cost = fmaf(-inter, ru, base);
                    r[t] = valid[t] ? cost : BIGV;
                }
                reinterpret_cast<float4*>(obase + (size_t)ii * QQ)[0] = res;
            }
        }
        { // remainder ii = 24
            const int ii = 24;
            float4 pc = s_cb[ii];
            float  a1 = s_a1[ii];
            float4 res;
            float* r = &res.x;
            #pragma unroll
            for (int t = 0; t < 4; t++) {
                float np = npp[t][ii];
                float d0 = pc.x - gcx[t], d1 = pc.y - gcy[t];
                float d2 = pc.z - hgz[t], d3 = pc.w - hgw[t];
                float u = fabsf(d0) + fabsf(d1);
                float v = fabsf(d2) + fabsf(d3);
                float mx = fmaxf(fabsf(d0), fabsf(d2));
                float my = fmaxf(fabsf(d1), fabsf(d3));
                float sz = pc.z + hgz[t], sw = pc.w + hgw[t];
                float iwu = sz - mx, ihu = sw - my;
                float ew  = sz + mx, eh  = sw + my;
                float iw = fmaxf(iwu, 0.0f), ih = fmaxf(ihu, 0.0f);
                float inter = iw * ih;
                float enc   = ew * eh;
                float uni   = (a1 + a2[t]) - inter;
                float ru = fast_rcp(uni);
                float re = fast_rcp(enc);
                float base = fmaf(v, 0.5f, np);
                base = fmaf(u, 0.25f, base);
                base = fmaf(-uni, re, base);
                float cost = fmaf(-inter, ru, base);
                r[t] = valid[t] ? cost : BIGV;
            }
            reinterpret_cast<float4*>(obase + (size_t)ii * QQ)[0] = res;
        }
    } else if (lane < TI) {
        // ==== warp 7: strip j = 896..899, one i-row (ii = lane) per lane ====
        const int ii = lane;
        const int j0 = 896;
        float4 pc = s_cb[ii];
        float  a1 = s_a1[ii];
        float4 res;
        float* r = &res.x;
        #pragma unroll
        for (int t = 0; t < 4; t++) {
            float4 g = reinterpret_cast<const float4*>(boxes)[b * QQ + j0 + t];
            float np = s_npT[labels[b * QQ + j0 + t]][ii];
            bool  vd = area[b * QQ + j0 + t] > 0.0f;
            float hgz = 0.5f * g.z, hgw = 0.5f * g.w;
            float a2 = g.z * g.w;
            float d0 = pc.x - g.x, d1 = pc.y - g.y;
            float d2 = pc.z - hgz, d3 = pc.w - hgw;
            float u = fabsf(d0) + fabsf(d1);
            float v = fabsf(d2) + fabsf(d3);
            float mx = fmaxf(fabsf(d0), fabsf(d2));
            float my = fmaxf(fabsf(d1), fabsf(d3));
            float sz = pc.z + hgz, sw = pc.w + hgw;
            float iwu = sz - mx, ihu = sw - my;
            float ew  = sz + mx, eh  = sw + my;
            float iw = fmaxf(iwu, 0.0f), ih = fmaxf(ihu, 0.0f);
            float inter = iw * ih;
            float enc   = ew * eh;
            float uni   = (a1 + a2) - inter;
            float ru = fast_rcp(uni);
            float re = fast_rcp(enc);
            float base = fmaf(v, 0.5f, np);
            base = fmaf(u, 0.25f, base);
            base = fmaf(-uni, re, base);
            float cost = fmaf(-inter, ru, base);
            r[t] = vd ? cost : BIGV;
        }
        float* op = out + ((size_t)(b * QQ + i0 + ii)) * QQ + j0;
        reinterpret_cast<float4*>(op)[0] = res;
    }
}

extern "C" void kernel_launch(void* const* d_in, const int* in_sizes, int n_in,
                              void* d_out, int out_size) {
    const float* pred_logits = (const float*)d_in[0];  // [B,Q,C]
    const float* pred_boxes  = (const float*)d_in[1];  // [B,Q,4]
    const float* boxes       = (const float*)d_in[2];  // [B,Q,4]
    const float* area        = (const float*)d_in[3];  // [B,Q]
    const int*   labels      = (const int*)d_in[4];    // [B,Q]
    float* out = (float*)d_out;                        // [B,Q,Q]

    dim3 grid(QQ / TI, BB);             // (36, 32) = 1152 blocks ~ 2 waves
    cost_kernel<<<grid, 256>>>(pred_logits, pred_boxes, boxes, area, labels, out);
}